// round 16
// baseline (speedup 1.0000x reference)
#include <cuda_runtime.h>
#include <cuda_bf16.h>
#include <cstdint>

#define N_CLASSES 26
#define IMG 68
#define BATCH 8192
#define NEXP 64
#define FC1N 500
#define FLATN 1960
#define PBLK 260

// scratch (device globals; no allocation allowed; zero-initialized)
__device__ __align__(16) float g_p1[N_CLASSES * 5 * 32 * 32];
__device__ __align__(16) float g_hcls[N_CLASSES * FLATN];
__device__ __align__(16) float g_u[N_CLASSES * 512];          // k-padded to 512
__device__ __align__(16) float2 g_wx[512];                    // k-padded
// bf16 split of fc2_w, chunked: [chunk 0..3][part hi/lo][64 e][136]
__device__ __align__(16) __nv_bfloat16 g_wbf[4 * 2 * 64 * 136];
__device__ unsigned g_count;   // monotonic grid-barrier counter (never reset)

// ---------------------------------------------------------------------------
// helpers
// ---------------------------------------------------------------------------
__device__ __forceinline__ uint32_t smem_to_u32(const void* p) {
    uint32_t a;
    asm("{ .reg .u64 t; cvta.to.shared.u64 t, %1; cvt.u32.u64 %0, t; }"
        : "=r"(a) : "l"(p));
    return a;
}
__device__ __forceinline__ void ldm_x4(uint32_t& r0, uint32_t& r1,
                                       uint32_t& r2, uint32_t& r3, uint32_t addr) {
    asm volatile("ldmatrix.sync.aligned.m8n8.x4.shared.b16 {%0,%1,%2,%3}, [%4];"
                 : "=r"(r0), "=r"(r1), "=r"(r2), "=r"(r3) : "r"(addr));
}
__device__ __forceinline__ void mma16816(float* c, const uint32_t* a,
                                         uint32_t b0, uint32_t b1) {
    asm volatile(
        "mma.sync.aligned.m16n8k16.row.col.f32.bf16.bf16.f32 "
        "{%0,%1,%2,%3}, {%4,%5,%6,%7}, {%8,%9}, {%0,%1,%2,%3};"
        : "+f"(c[0]), "+f"(c[1]), "+f"(c[2]), "+f"(c[3])
        : "r"(a[0]), "r"(a[1]), "r"(a[2]), "r"(a[3]), "r"(b0), "r"(b1));
}
#define CP_ASYNC16(dst, src) \
    asm volatile("cp.async.cg.shared.global [%0], [%1], 16;" \
                 :: "r"(dst), "l"(src) : "memory")
#define CP_COMMIT() asm volatile("cp.async.commit_group;" ::: "memory")

// grid-wide barrier (prep kernel only): monotonic counter, replay-safe.
__device__ __forceinline__ void gridbar() {
    __syncthreads();
    if (threadIdx.x == 0) {
        __threadfence();
        unsigned arrival = atomicAdd(&g_count, 1u);
        unsigned target = (arrival / PBLK + 1u) * PBLK;
        while (atomicAdd(&g_count, 0u) < target) { }
        __threadfence();
    }
    __syncthreads();
}

// ---------------------------------------------------------------------------
// Kernel P: prep (conv1 + conv2 + fc1 + side work), grid = 260 x 256,
// smem 21 KB, high occupancy -> grid barrier trivially safe.
// ---------------------------------------------------------------------------
#define PSMEM (21 * 1024)
__global__ void __launch_bounds__(256, 4)
prep_kernel(const float* __restrict__ images,
            const float* __restrict__ conv1_w, const float* __restrict__ conv1_b,
            const float* __restrict__ conv2_w, const float* __restrict__ conv2_b,
            const float* __restrict__ fc1_w, const float* __restrict__ fc1_b,
            const float* __restrict__ fc2_w) {
    extern __shared__ float psm[];
    int tid = threadIdx.x, lane = tid & 31, warp = tid >> 5;
    int b = blockIdx.x;

    // ============ Phase A: fc2 split + wx + u-pad + conv1 (b<130) =========
    {
        for (int gt = b * 256 + tid; gt < 65536; gt += PBLK * 256) {
            int cch = gt >> 14, part = (gt >> 13) & 1;
            int e = (gt >> 7) & 63, kk = gt & 127;
            int k = cch * 128 + kk;
            float val = (k < FC1N) ? fc2_w[e * FC1N + k] : 0.f;
            __nv_bfloat16 hi = __float2bfloat16(val);
            __nv_bfloat16 res = __float2bfloat16(val - __bfloat162float(hi));
            g_wbf[((cch * 2 + part) * 64 + e) * 136 + kk] = part ? res : hi;
        }
        int gt = b * 256 + tid;
        if (gt < 512) {
            float2 v = make_float2(0.f, 0.f);
            if (gt < FC1N) {
                v.x = fc1_w[gt * 1962 + 1960];
                v.y = fc1_w[gt * 1962 + 1961];
            }
            g_wx[gt] = v;
        }
        if (b == 259 && tid < N_CLASSES * 12) {
            int cls = tid / 12, kk = tid % 12;
            g_u[cls * 512 + 500 + kk] = 0.f;
        }
        if (b < N_CLASSES * 5) {
            float* s_img = psm;              // 18.5 KB
            float* s_w = s_img + IMG * IMG;
            int c = b / 5, ch = b % 5;
            const float* img = images + c * IMG * IMG;
            for (int i = tid; i < IMG * IMG; i += 256) s_img[i] = img[i];
            if (tid < 25) s_w[tid] = conv1_w[ch * 25 + tid];
            __syncthreads();
            float bb = conv1_b[ch];
            float wr[25];
#pragma unroll
            for (int i = 0; i < 25; i++) wr[i] = s_w[i];
            float* outp = g_p1 + (c * 5 + ch) * 1024;
            for (int i = tid; i < 1024; i += 256) {
                int oy = i >> 5, ox = i & 31;
                int y0 = 2 * oy, x0 = 2 * ox;
                float p[6][6];
#pragma unroll
                for (int r = 0; r < 6; r++)
#pragma unroll
                    for (int cc = 0; cc < 6; cc++)
                        p[r][cc] = s_img[(y0 + r) * IMG + x0 + cc];
                float a00 = bb, a01 = bb, a10 = bb, a11 = bb;
#pragma unroll
                for (int ky = 0; ky < 5; ky++)
#pragma unroll
                    for (int kx = 0; kx < 5; kx++) {
                        float w = wr[ky * 5 + kx];
                        a00 = fmaf(p[ky][kx], w, a00);
                        a01 = fmaf(p[ky][kx + 1], w, a01);
                        a10 = fmaf(p[ky + 1][kx], w, a10);
                        a11 = fmaf(p[ky + 1][kx + 1], w, a11);
                    }
                outp[i] = fmaxf(fmaxf(fmaxf(a00, a01), fmaxf(a10, a11)), 0.f);
            }
        }
    }
    gridbar();

    // ============ Phase B: conv2 (task = b, exactly 260 tasks) ============
    {
        float* s_p1 = psm;                   // 20 KB
        float* s_w = s_p1 + 5 * 1024;
        int c = b / 10, co = b % 10;
        for (int i = tid; i < 5120; i += 256) s_p1[i] = g_p1[c * 5120 + i];
        if (tid < 125) s_w[tid] = conv2_w[co * 125 + tid];
        __syncthreads();
        float bb = conv2_b[co];
        for (int i = tid; i < 196; i += 256) {
            int oy = i / 14, ox = i % 14;
            int y0 = 2 * oy, x0 = 2 * ox;
            float a00 = bb, a01 = bb, a10 = bb, a11 = bb;
#pragma unroll
            for (int ci = 0; ci < 5; ci++) {
                const float* basep = s_p1 + ci * 1024 + y0 * 32 + x0;
                float p[6][6];
#pragma unroll
                for (int r = 0; r < 6; r++)
#pragma unroll
                    for (int cc = 0; cc < 6; cc++) p[r][cc] = basep[r * 32 + cc];
                const float* wb = s_w + ci * 25;
#pragma unroll
                for (int ky = 0; ky < 5; ky++)
#pragma unroll
                    for (int kx = 0; kx < 5; kx++) {
                        float w = wb[ky * 5 + kx];
                        a00 = fmaf(p[ky][kx], w, a00);
                        a01 = fmaf(p[ky][kx + 1], w, a01);
                        a10 = fmaf(p[ky + 1][kx], w, a10);
                        a11 = fmaf(p[ky + 1][kx + 1], w, a11);
                    }
            }
            g_hcls[c * FLATN + co * 196 + i] =
                fmaxf(fmaxf(fmaxf(a00, a01), fmaxf(a10, a11)), 0.f);
        }
    }
    gridbar();

    // ============ Phase C: fc1 warp-per-dot (b<250, 2 out rows each) ======
    if (b < 250) {
        float* smW = psm;   // [2][1964] = 15.7 KB
        __syncthreads();    // smem reuse from phase B
        for (int i = tid; i < 2 * 981; i += 256) {
            int r = i / 981, k2 = i - r * 981;
            *(float2*)(smW + r * 1964 + 2 * k2) =
                ((const float2*)(fc1_w + (long)(2 * b + r) * 1962))[k2];
        }
        __syncthreads();
        for (int p = warp; p < 2 * N_CLASSES; p += 8) {
            int cls = p >> 1, outL = p & 1;
            int outn = 2 * b + outL;
            const float4* hc = (const float4*)(g_hcls + cls * FLATN);
            const float4* wr = (const float4*)(smW + outL * 1964);
            float acc = 0.f;
            for (int q = lane; q < 490; q += 32) {
                float4 h = hc[q], w = wr[q];
                acc += h.x * w.x + h.y * w.y + h.z * w.z + h.w * w.w;
            }
#pragma unroll
            for (int off = 16; off; off >>= 1) acc += __shfl_xor_sync(~0u, acc, off);
            if (lane == 0) g_u[cls * 512 + outn] = acc + fc1_b[outn];
        }
    }
}

// ---------------------------------------------------------------------------
// Kernel M: HMMA MoE — round-13 body VERBATIM (proven 15.7 us).
// grid = 256 (32 samples each), block = 256 (8 warps), smem 87 KB.
// ---------------------------------------------------------------------------
#define LR 68
#define SM_B 2048
#define BCH 34816
#define B_PARTB 17408
#define SM_A (SM_B + 2 * BCH)      // 71680
#define A_PARTB 8704
#define SMEMC (SM_A + 2 * A_PARTB) // 89088

__global__ void __launch_bounds__(256, 2)
moe_kernel(const float* __restrict__ x, const int* __restrict__ cls_idx,
           const float* __restrict__ fc2_b,
           const float* __restrict__ A_B, const float* __restrict__ A_C,
           const float* __restrict__ x_tar, float* __restrict__ out) {
    extern __shared__ char smem[];
    uint32_t smem_u32 = smem_to_u32(smem);
    float* misc = (float*)smem;
    float* Gs = misc;               // [64][4]
    float* b2s = misc + 256;        // [64]
    float* sx0 = misc + 320;        // [32]
    float* sx1 = misc + 352;
    float* sd0 = misc + 384;
    float* sd1 = misc + 416;
    int* scls = (int*)(misc + 448); // [32]
    float* Ls = (float*)(smem + SM_A);

    int tid = threadIdx.x, lane = tid & 31, warp = tid >> 5;
    int base = blockIdx.x * 32;

    if (tid < 256) Gs[tid] = A_B[tid] + A_C[tid];
    if (tid >= 64 && tid < 128) b2s[tid - 64] = fc2_b[tid - 64];
    if (tid < 32) {
        int s = base + tid;
        float x0v = x[2 * s], x1v = x[2 * s + 1];
        sx0[tid] = x0v; sx1[tid] = x1v;
        sd0[tid] = x_tar[0] - x0v;
        sd1[tid] = x_tar[1] - x1v;
        scls[tid] = cls_idx[s];
    }
    {
        const char* src = (const char*)g_wbf;
        uint32_t dst = smem_u32 + SM_B;
        for (int i = tid; i < 2176; i += 256)
            CP_ASYNC16(dst + i * 16, src + i * 16);
        CP_COMMIT();
    }
    __syncthreads();

    int m0 = (warp & 1) * 16;
    int n0 = (warp >> 1) * 16;
    float c0[4] = {0.f, 0.f, 0.f, 0.f};
    float c1[4] = {0.f, 0.f, 0.f, 0.f};

    uint32_t aRow = (uint32_t)(lane & 15);
    uint32_t aCol = (uint32_t)((lane >> 4) * 16);
    uint32_t aHiBase = smem_u32 + SM_A + (m0 + aRow) * 272 + aCol;
    uint32_t bRow = (uint32_t)(n0 + ((lane >> 4) << 3) + (lane & 7));
    uint32_t bCol = (uint32_t)(((lane >> 3) & 1) * 16);
    uint32_t bHiOff = bRow * 272 + bCol;

    const float4* u4 = (const float4*)g_u;
    const float4* wx4 = (const float4*)g_wx;

    for (int c = 0; c < 4; c++) {
        if (c < 3) {
            const char* src = (const char*)g_wbf + (c + 1) * BCH;
            uint32_t dst = smem_u32 + SM_B + ((c + 1) & 1) * BCH;
            for (int i = tid; i < 2176; i += 256)
                CP_ASYNC16(dst + i * 16, src + i * 16);
            CP_COMMIT();
        }
#pragma unroll
        for (int j = 0; j < 4; j++) {
            int s = warp + 8 * j;
            int cls = scls[s];
            float xx0 = sx0[s], xx1 = sx1[s];
            float4 uv = u4[cls * 128 + c * 32 + lane];
            float4 w0 = wx4[c * 64 + 2 * lane];
            float4 w1 = wx4[c * 64 + 2 * lane + 1];
            float h0 = fmaxf(fmaf(xx0, w0.x, fmaf(xx1, w0.y, uv.x)), 0.f);
            float h1 = fmaxf(fmaf(xx0, w0.z, fmaf(xx1, w0.w, uv.y)), 0.f);
            float h2 = fmaxf(fmaf(xx0, w1.x, fmaf(xx1, w1.y, uv.z)), 0.f);
            float h3 = fmaxf(fmaf(xx0, w1.z, fmaf(xx1, w1.w, uv.w)), 0.f);
            __nv_bfloat16 b0 = __float2bfloat16(h0);
            __nv_bfloat16 b1 = __float2bfloat16(h1);
            __nv_bfloat16 b2 = __float2bfloat16(h2);
            __nv_bfloat16 b3 = __float2bfloat16(h3);
            __nv_bfloat16 l0 = __float2bfloat16(h0 - __bfloat162float(b0));
            __nv_bfloat16 l1 = __float2bfloat16(h1 - __bfloat162float(b1));
            __nv_bfloat16 l2 = __float2bfloat16(h2 - __bfloat162float(b2));
            __nv_bfloat16 l3 = __float2bfloat16(h3 - __bfloat162float(b3));
            __nv_bfloat162 hA(b0, b1), hB(b2, b3), lA(l0, l1), lB(l2, l3);
            uint2 hv, lv;
            hv.x = *(uint32_t*)&hA; hv.y = *(uint32_t*)&hB;
            lv.x = *(uint32_t*)&lA; lv.y = *(uint32_t*)&lB;
            char* pa = smem + SM_A + s * 272 + lane * 8;
            *(uint2*)pa = hv;
            *(uint2*)(pa + A_PARTB) = lv;
        }
        if (c < 3) asm volatile("cp.async.wait_group 1;" ::: "memory");
        else       asm volatile("cp.async.wait_group 0;" ::: "memory");
        __syncthreads();

        uint32_t aHi = aHiBase;
        uint32_t bHi = smem_u32 + SM_B + (c & 1) * BCH + bHiOff;
#pragma unroll
        for (int ks = 0; ks < 8; ks++) {
            uint32_t ah[4], al[4], bh[4], bl[4];
            ldm_x4(ah[0], ah[1], ah[2], ah[3], aHi);
            ldm_x4(al[0], al[1], al[2], al[3], aHi + A_PARTB);
            ldm_x4(bh[0], bh[1], bh[2], bh[3], bHi);
            ldm_x4(bl[0], bl[1], bl[2], bl[3], bHi + B_PARTB);
            mma16816(c0, ah, bh[0], bh[1]);
            mma16816(c1, ah, bh[2], bh[3]);
            mma16816(c0, al, bh[0], bh[1]);
            mma16816(c1, al, bh[2], bh[3]);
            mma16816(c0, ah, bl[0], bl[1]);
            mma16816(c1, ah, bl[2], bl[3]);
            aHi += 32;
            bHi += 32;
        }
        __syncthreads();
    }

    {
        int r0 = m0 + (lane >> 2);
        int cb = n0 + (lane & 3) * 2;
        Ls[r0 * LR + cb] = c0[0];
        Ls[r0 * LR + cb + 1] = c0[1];
        Ls[(r0 + 8) * LR + cb] = c0[2];
        Ls[(r0 + 8) * LR + cb + 1] = c0[3];
        Ls[r0 * LR + cb + 8] = c1[0];
        Ls[r0 * LR + cb + 9] = c1[1];
        Ls[(r0 + 8) * LR + cb + 8] = c1[2];
        Ls[(r0 + 8) * LR + cb + 9] = c1[3];
    }
    __syncthreads();

    for (int s = warp; s < 32; s += 8) {
        float l0 = Ls[s * LR + lane] + b2s[lane];
        float l1 = Ls[s * LR + 32 + lane] + b2s[32 + lane];
        float m = fmaxf(l0, l1);
#pragma unroll
        for (int off = 16; off; off >>= 1) m = fmaxf(m, __shfl_xor_sync(~0u, m, off));
        float ee0 = __expf(l0 - m), ee1 = __expf(l1 - m);
        float d0 = sd0[s], d1 = sd1[s];
        const float* G0 = Gs + lane * 4;
        const float* G1 = Gs + (lane + 32) * 4;
        float y0 = ee0 * (G0[0] * d0 + G0[1] * d1) + ee1 * (G1[0] * d0 + G1[1] * d1);
        float y1 = ee0 * (G0[2] * d0 + G0[3] * d1) + ee1 * (G1[2] * d0 + G1[3] * d1);
        float Z = ee0 + ee1;
#pragma unroll
        for (int off = 16; off; off >>= 1) {
            y0 += __shfl_xor_sync(~0u, y0, off);
            y1 += __shfl_xor_sync(~0u, y1, off);
            Z += __shfl_xor_sync(~0u, Z, off);
        }
        if (lane == 0) {
            float inv = 1.f / Z;
            out[2 * (base + s) + 0] = y0 * inv;
            out[2 * (base + s) + 1] = y1 * inv;
        }
    }
}

// ---------------------------------------------------------------------------
extern "C" void kernel_launch(void* const* d_in, const int* in_sizes, int n_in,
                              void* d_out, int out_size) {
    const float* x       = (const float*)d_in[0];
    const int*   cls     = (const int*)d_in[1];
    const float* images  = (const float*)d_in[2];
    const float* conv1_w = (const float*)d_in[3];
    const float* conv1_b = (const float*)d_in[4];
    const float* conv2_w = (const float*)d_in[5];
    const float* conv2_b = (const float*)d_in[6];
    const float* fc1_w   = (const float*)d_in[7];
    const float* fc1_b   = (const float*)d_in[8];
    const float* fc2_w   = (const float*)d_in[9];
    const float* fc2_b   = (const float*)d_in[10];
    const float* A_B     = (const float*)d_in[11];
    const float* A_C     = (const float*)d_in[12];
    const float* x_tar   = (const float*)d_in[13];
    float* out = (float*)d_out;

    cudaFuncSetAttribute(prep_kernel, cudaFuncAttributeMaxDynamicSharedMemorySize,
                         PSMEM);
    cudaFuncSetAttribute(moe_kernel, cudaFuncAttributeMaxDynamicSharedMemorySize,
                         SMEMC);

    prep_kernel<<<PBLK, 256, PSMEM>>>(images, conv1_w, conv1_b,
                                      conv2_w, conv2_b, fc1_w, fc1_b, fc2_w);
    moe_kernel<<<BATCH / 32, 256, SMEMC>>>(x, cls, fc2_b, A_B, A_C, x_tar, out);
    (void)in_sizes; (void)n_in; (void)out_size;
}

// round 17
// speedup vs baseline: 1.2192x; 1.2192x over previous
#include <cuda_runtime.h>
#include <cuda_bf16.h>
#include <cstdint>

#define N_CLASSES 26
#define IMG 68
#define BATCH 8192
#define NEXP 64
#define FC1N 500
#define FLATN 1960
#define K1BLK 260

// scratch (device globals; no allocation allowed; zero-initialized)
__device__ __align__(16) float g_p1[N_CLASSES * 5 * 32 * 32];
__device__ __align__(16) float g_hcls[N_CLASSES * FLATN];
__device__ __align__(16) float g_u[N_CLASSES * 512];          // k-padded to 512
__device__ __align__(16) float2 g_wx[512];                    // k-padded
// bf16 split of fc2_w, chunked: [chunk 0..3][part hi/lo][64 e][136]
__device__ __align__(16) __nv_bfloat16 g_wbf[4 * 2 * 64 * 136];
__device__ unsigned g_count;   // monotonic grid-barrier counter (never reset)

// ---------------------------------------------------------------------------
// helpers
// ---------------------------------------------------------------------------
__device__ __forceinline__ uint32_t smem_to_u32(const void* p) {
    uint32_t a;
    asm("{ .reg .u64 t; cvta.to.shared.u64 t, %1; cvt.u32.u64 %0, t; }"
        : "=r"(a) : "l"(p));
    return a;
}
__device__ __forceinline__ void ldm_x4(uint32_t& r0, uint32_t& r1,
                                       uint32_t& r2, uint32_t& r3, uint32_t addr) {
    asm volatile("ldmatrix.sync.aligned.m8n8.x4.shared.b16 {%0,%1,%2,%3}, [%4];"
                 : "=r"(r0), "=r"(r1), "=r"(r2), "=r"(r3) : "r"(addr));
}
__device__ __forceinline__ void mma16816(float* c, const uint32_t* a,
                                         uint32_t b0, uint32_t b1) {
    asm volatile(
        "mma.sync.aligned.m16n8k16.row.col.f32.bf16.bf16.f32 "
        "{%0,%1,%2,%3}, {%4,%5,%6,%7}, {%8,%9}, {%0,%1,%2,%3};"
        : "+f"(c[0]), "+f"(c[1]), "+f"(c[2]), "+f"(c[3])
        : "r"(a[0]), "r"(a[1]), "r"(a[2]), "r"(a[3]), "r"(b0), "r"(b1));
}
#define CP_ASYNC16(dst, src) \
    asm volatile("cp.async.cg.shared.global [%0], [%1], 16;" \
                 :: "r"(dst), "l"(src) : "memory")
#define CP_COMMIT() asm volatile("cp.async.commit_group;" ::: "memory")

// grid-wide barrier (K1 only): monotonic counter, replay-safe.
__device__ __forceinline__ void gridbar() {
    __syncthreads();
    if (threadIdx.x == 0) {
        __threadfence();
        unsigned arrival = atomicAdd(&g_count, 1u);
        unsigned target = (arrival / K1BLK + 1u) * K1BLK;
        while (atomicAdd(&g_count, 0u) < target) { }
        __threadfence();
    }
    __syncthreads();
}

// ---------------------------------------------------------------------------
// Kernel 1: conv1 + conv2 + fc2-split side work, one grid barrier.
// grid = 260 x 512, smem 21 KB, launch_bounds(512,2) -> 296 resident >= 260.
// ---------------------------------------------------------------------------
#define K1SMEM (21 * 1024)
__global__ void __launch_bounds__(512, 2)
conv_kernel(const float* __restrict__ images,
            const float* __restrict__ conv1_w, const float* __restrict__ conv1_b,
            const float* __restrict__ conv2_w, const float* __restrict__ conv2_b,
            const float* __restrict__ fc1_w,
            const float* __restrict__ fc2_w) {
    extern __shared__ float psm[];
    int tid = threadIdx.x;
    int b = blockIdx.x;

    // ===== Phase A: fc2 split + wx + u-pad + conv1 (b < 130, proven body) ==
    {
        int gt = b * 512 + tid;
        if (gt < 65536) {
            int cch = gt >> 14, part = (gt >> 13) & 1;
            int e = (gt >> 7) & 63, kk = gt & 127;
            int k = cch * 128 + kk;
            float val = (k < FC1N) ? fc2_w[e * FC1N + k] : 0.f;
            __nv_bfloat16 hi = __float2bfloat16(val);
            __nv_bfloat16 res = __float2bfloat16(val - __bfloat162float(hi));
            g_wbf[((cch * 2 + part) * 64 + e) * 136 + kk] = part ? res : hi;
        }
        if (gt < 512) {
            float2 v = make_float2(0.f, 0.f);
            if (gt < FC1N) {
                v.x = fc1_w[gt * 1962 + 1960];
                v.y = fc1_w[gt * 1962 + 1961];
            }
            g_wx[gt] = v;
        }
        if (b == 259 && tid < N_CLASSES * 12) {
            int cls = tid / 12, kk = tid % 12;
            g_u[cls * 512 + 500 + kk] = 0.f;   // zero k-pad
        }
        if (b < N_CLASSES * 5) {
            float* s_img = psm;              // 18.5 KB
            float* s_w = s_img + IMG * IMG;
            int c = b / 5, ch = b % 5;
            const float* img = images + c * IMG * IMG;
            for (int i = tid; i < IMG * IMG; i += 512) s_img[i] = img[i];
            if (tid < 25) s_w[tid] = conv1_w[ch * 25 + tid];
            __syncthreads();
            float bb = conv1_b[ch];
            float wr[25];
#pragma unroll
            for (int i = 0; i < 25; i++) wr[i] = s_w[i];
            float* outp = g_p1 + (c * 5 + ch) * 1024;
            for (int i = tid; i < 1024; i += 512) {
                int oy = i >> 5, ox = i & 31;
                int y0 = 2 * oy, x0 = 2 * ox;
                float p[6][6];
#pragma unroll
                for (int r = 0; r < 6; r++)
#pragma unroll
                    for (int cc = 0; cc < 6; cc++)
                        p[r][cc] = s_img[(y0 + r) * IMG + x0 + cc];
                float a00 = bb, a01 = bb, a10 = bb, a11 = bb;
#pragma unroll
                for (int ky = 0; ky < 5; ky++)
#pragma unroll
                    for (int kx = 0; kx < 5; kx++) {
                        float w = wr[ky * 5 + kx];
                        a00 = fmaf(p[ky][kx], w, a00);
                        a01 = fmaf(p[ky][kx + 1], w, a01);
                        a10 = fmaf(p[ky + 1][kx], w, a10);
                        a11 = fmaf(p[ky + 1][kx + 1], w, a11);
                    }
                outp[i] = fmaxf(fmaxf(fmaxf(a00, a01), fmaxf(a10, a11)), 0.f);
            }
        }
    }
    gridbar();

    // ===== Phase B: conv2 (task = b, exactly 260 tasks, proven body) ======
    {
        float* s_p1 = psm;                   // 20 KB
        float* s_w = s_p1 + 5 * 1024;
        int c = b / 10, co = b % 10;
        for (int i = tid; i < 5120; i += 512) s_p1[i] = g_p1[c * 5120 + i];
        if (tid < 125) s_w[tid] = conv2_w[co * 125 + tid];
        __syncthreads();
        float bb = conv2_b[co];
        for (int i = tid; i < 196; i += 512) {
            int oy = i / 14, ox = i % 14;
            int y0 = 2 * oy, x0 = 2 * ox;
            float a00 = bb, a01 = bb, a10 = bb, a11 = bb;
#pragma unroll
            for (int ci = 0; ci < 5; ci++) {
                const float* basep = s_p1 + ci * 1024 + y0 * 32 + x0;
                float p[6][6];
#pragma unroll
                for (int r = 0; r < 6; r++)
#pragma unroll
                    for (int cc = 0; cc < 6; cc++) p[r][cc] = basep[r * 32 + cc];
                const float* wb = s_w + ci * 25;
#pragma unroll
                for (int ky = 0; ky < 5; ky++)
#pragma unroll
                    for (int kx = 0; kx < 5; kx++) {
                        float w = wb[ky * 5 + kx];
                        a00 = fmaf(p[ky][kx], w, a00);
                        a01 = fmaf(p[ky][kx + 1], w, a01);
                        a10 = fmaf(p[ky + 1][kx], w, a10);
                        a11 = fmaf(p[ky + 1][kx + 1], w, a11);
                    }
            }
            g_hcls[c * FLATN + co * 196 + i] =
                fmaxf(fmaxf(fmaxf(a00, a01), fmaxf(a10, a11)), 0.f);
        }
    }
}

// ---------------------------------------------------------------------------
// Kernel 2: fc1 — round-13 smem-tiled body VERBATIM. grid = 128, block = 512.
// ---------------------------------------------------------------------------
#define WROWP 1964
#define FC1SMEM ((16 * WROWP + 8 * WROWP + 2048) * 4)
__global__ void __launch_bounds__(512, 1) fc1_kernel(const float* __restrict__ fc1_w,
                                                     const float* __restrict__ fc1_b) {
    extern __shared__ float sm[];
    float* smW = sm;                    // [16][1964]
    float* smH = smW + 16 * WROWP;      // [8][1964]
    float* pbuf = smH + 8 * WROWP;      // [2048]
    int tid = threadIdx.x;
    int ot = blockIdx.x & 31, ct = blockIdx.x >> 5;

    for (int idx = tid; idx < 16 * 980; idx += 512) {
        int r = idx / 980, k2 = idx - r * 980;
        int row = ot * 16 + r;
        float2 v = (row < FC1N)
                       ? ((const float2*)(fc1_w + (long)row * 1962))[k2]
                       : make_float2(0.f, 0.f);
        *(float2*)(smW + r * WROWP + 2 * k2) = v;
    }
    for (int idx = tid; idx < 8 * 490; idx += 512) {
        int r = idx / 490, q = idx - r * 490;
        int ci = ct * 8 + r;
        float4 v = (ci < N_CLASSES)
                       ? ((const float4*)(g_hcls + ci * FLATN))[q]
                       : make_float4(0.f, 0.f, 0.f, 0.f);
        *(float4*)(smH + r * WROWP + 4 * q) = v;
    }
    __syncthreads();

    int o = tid & 15, cg = (tid >> 4) & 1, kq = tid >> 5;  // kq 0..15
    const float4* wq = (const float4*)(smW + o * WROWP);
    const float4* h0 = (const float4*)(smH + (4 * cg + 0) * WROWP);
    const float4* h1 = (const float4*)(smH + (4 * cg + 1) * WROWP);
    const float4* h2 = (const float4*)(smH + (4 * cg + 2) * WROWP);
    const float4* h3 = (const float4*)(smH + (4 * cg + 3) * WROWP);
    float a0 = 0.f, a1 = 0.f, a2 = 0.f, a3 = 0.f;
    for (int q = kq; q < 490; q += 16) {
        float4 w = wq[q];
        float4 v0 = h0[q], v1 = h1[q], v2 = h2[q], v3 = h3[q];
        a0 = fmaf(w.x, v0.x, a0); a0 = fmaf(w.y, v0.y, a0);
        a0 = fmaf(w.z, v0.z, a0); a0 = fmaf(w.w, v0.w, a0);
        a1 = fmaf(w.x, v1.x, a1); a1 = fmaf(w.y, v1.y, a1);
        a1 = fmaf(w.z, v1.z, a1); a1 = fmaf(w.w, v1.w, a1);
        a2 = fmaf(w.x, v2.x, a2); a2 = fmaf(w.y, v2.y, a2);
        a2 = fmaf(w.z, v2.z, a2); a2 = fmaf(w.w, v2.w, a2);
        a3 = fmaf(w.x, v3.x, a3); a3 = fmaf(w.y, v3.y, a3);
        a3 = fmaf(w.z, v3.z, a3); a3 = fmaf(w.w, v3.w, a3);
    }
    pbuf[o + 16 * (4 * cg + 0) + 128 * kq] = a0;
    pbuf[o + 16 * (4 * cg + 1) + 128 * kq] = a1;
    pbuf[o + 16 * (4 * cg + 2) + 128 * kq] = a2;
    pbuf[o + 16 * (4 * cg + 3) + 128 * kq] = a3;
    __syncthreads();
    if (tid < 128) {
        int oo = tid & 15, cc = tid >> 4;
        float s = 0.f;
#pragma unroll
        for (int j = 0; j < 16; j++) s += pbuf[oo + 16 * cc + 128 * j];
        int cls = ct * 8 + cc;
        int outn = ot * 16 + oo;
        if (cls < N_CLASSES) {
            float val = 0.f;
            if (outn < FC1N) val = s + fc1_b[outn];
            g_u[cls * 512 + outn] = val;
        }
    }
}

// ---------------------------------------------------------------------------
// Kernel 3: HMMA MoE — round-13 body VERBATIM (proven 15.5 us).
// grid = 256 (32 samples each), block = 256 (8 warps), smem 87 KB.
// ---------------------------------------------------------------------------
#define LR 68
#define SM_B 2048
#define BCH 34816
#define B_PARTB 17408
#define SM_A (SM_B + 2 * BCH)      // 71680
#define A_PARTB 8704
#define SMEMC (SM_A + 2 * A_PARTB) // 89088

__global__ void __launch_bounds__(256, 2)
moe_kernel(const float* __restrict__ x, const int* __restrict__ cls_idx,
           const float* __restrict__ fc2_b,
           const float* __restrict__ A_B, const float* __restrict__ A_C,
           const float* __restrict__ x_tar, float* __restrict__ out) {
    extern __shared__ char smem[];
    uint32_t smem_u32 = smem_to_u32(smem);
    float* misc = (float*)smem;
    float* Gs = misc;               // [64][4]
    float* b2s = misc + 256;        // [64]
    float* sx0 = misc + 320;        // [32]
    float* sx1 = misc + 352;
    float* sd0 = misc + 384;
    float* sd1 = misc + 416;
    int* scls = (int*)(misc + 448); // [32]
    float* Ls = (float*)(smem + SM_A);

    int tid = threadIdx.x, lane = tid & 31, warp = tid >> 5;
    int base = blockIdx.x * 32;

    if (tid < 256) Gs[tid] = A_B[tid] + A_C[tid];
    if (tid >= 64 && tid < 128) b2s[tid - 64] = fc2_b[tid - 64];
    if (tid < 32) {
        int s = base + tid;
        float x0v = x[2 * s], x1v = x[2 * s + 1];
        sx0[tid] = x0v; sx1[tid] = x1v;
        sd0[tid] = x_tar[0] - x0v;
        sd1[tid] = x_tar[1] - x1v;
        scls[tid] = cls_idx[s];
    }
    {
        const char* src = (const char*)g_wbf;
        uint32_t dst = smem_u32 + SM_B;
        for (int i = tid; i < 2176; i += 256)
            CP_ASYNC16(dst + i * 16, src + i * 16);
        CP_COMMIT();
    }
    __syncthreads();

    int m0 = (warp & 1) * 16;
    int n0 = (warp >> 1) * 16;
    float c0[4] = {0.f, 0.f, 0.f, 0.f};
    float c1[4] = {0.f, 0.f, 0.f, 0.f};

    uint32_t aRow = (uint32_t)(lane & 15);
    uint32_t aCol = (uint32_t)((lane >> 4) * 16);
    uint32_t aHiBase = smem_u32 + SM_A + (m0 + aRow) * 272 + aCol;
    uint32_t bRow = (uint32_t)(n0 + ((lane >> 4) << 3) + (lane & 7));
    uint32_t bCol = (uint32_t)(((lane >> 3) & 1) * 16);
    uint32_t bHiOff = bRow * 272 + bCol;

    const float4* u4 = (const float4*)g_u;
    const float4* wx4 = (const float4*)g_wx;

    for (int c = 0; c < 4; c++) {
        if (c < 3) {
            const char* src = (const char*)g_wbf + (c + 1) * BCH;
            uint32_t dst = smem_u32 + SM_B + ((c + 1) & 1) * BCH;
            for (int i = tid; i < 2176; i += 256)
                CP_ASYNC16(dst + i * 16, src + i * 16);
            CP_COMMIT();
        }
#pragma unroll
        for (int j = 0; j < 4; j++) {
            int s = warp + 8 * j;
            int cls = scls[s];
            float xx0 = sx0[s], xx1 = sx1[s];
            float4 uv = u4[cls * 128 + c * 32 + lane];
            float4 w0 = wx4[c * 64 + 2 * lane];
            float4 w1 = wx4[c * 64 + 2 * lane + 1];
            float h0 = fmaxf(fmaf(xx0, w0.x, fmaf(xx1, w0.y, uv.x)), 0.f);
            float h1 = fmaxf(fmaf(xx0, w0.z, fmaf(xx1, w0.w, uv.y)), 0.f);
            float h2 = fmaxf(fmaf(xx0, w1.x, fmaf(xx1, w1.y, uv.z)), 0.f);
            float h3 = fmaxf(fmaf(xx0, w1.z, fmaf(xx1, w1.w, uv.w)), 0.f);
            __nv_bfloat16 b0 = __float2bfloat16(h0);
            __nv_bfloat16 b1 = __float2bfloat16(h1);
            __nv_bfloat16 b2 = __float2bfloat16(h2);
            __nv_bfloat16 b3 = __float2bfloat16(h3);
            __nv_bfloat16 l0 = __float2bfloat16(h0 - __bfloat162float(b0));
            __nv_bfloat16 l1 = __float2bfloat16(h1 - __bfloat162float(b1));
            __nv_bfloat16 l2 = __float2bfloat16(h2 - __bfloat162float(b2));
            __nv_bfloat16 l3 = __float2bfloat16(h3 - __bfloat162float(b3));
            __nv_bfloat162 hA(b0, b1), hB(b2, b3), lA(l0, l1), lB(l2, l3);
            uint2 hv, lv;
            hv.x = *(uint32_t*)&hA; hv.y = *(uint32_t*)&hB;
            lv.x = *(uint32_t*)&lA; lv.y = *(uint32_t*)&lB;
            char* pa = smem + SM_A + s * 272 + lane * 8;
            *(uint2*)pa = hv;
            *(uint2*)(pa + A_PARTB) = lv;
        }
        if (c < 3) asm volatile("cp.async.wait_group 1;" ::: "memory");
        else       asm volatile("cp.async.wait_group 0;" ::: "memory");
        __syncthreads();

        uint32_t aHi = aHiBase;
        uint32_t bHi = smem_u32 + SM_B + (c & 1) * BCH + bHiOff;
#pragma unroll
        for (int ks = 0; ks < 8; ks++) {
            uint32_t ah[4], al[4], bh[4], bl[4];
            ldm_x4(ah[0], ah[1], ah[2], ah[3], aHi);
            ldm_x4(al[0], al[1], al[2], al[3], aHi + A_PARTB);
            ldm_x4(bh[0], bh[1], bh[2], bh[3], bHi);
            ldm_x4(bl[0], bl[1], bl[2], bl[3], bHi + B_PARTB);
            mma16816(c0, ah, bh[0], bh[1]);
            mma16816(c1, ah, bh[2], bh[3]);
            mma16816(c0, al, bh[0], bh[1]);
            mma16816(c1, al, bh[2], bh[3]);
            mma16816(c0, ah, bl[0], bl[1]);
            mma16816(c1, ah, bl[2], bl[3]);
            aHi += 32;
            bHi += 32;
        }
        __syncthreads();
    }

    {
        int r0 = m0 + (lane >> 2);
        int cb = n0 + (lane & 3) * 2;
        Ls[r0 * LR + cb] = c0[0];
        Ls[r0 * LR + cb + 1] = c0[1];
        Ls[(r0 + 8) * LR + cb] = c0[2];
        Ls[(r0 + 8) * LR + cb + 1] = c0[3];
        Ls[r0 * LR + cb + 8] = c1[0];
        Ls[r0 * LR + cb + 9] = c1[1];
        Ls[(r0 + 8) * LR + cb + 8] = c1[2];
        Ls[(r0 + 8) * LR + cb + 9] = c1[3];
    }
    __syncthreads();

    for (int s = warp; s < 32; s += 8) {
        float l0 = Ls[s * LR + lane] + b2s[lane];
        float l1 = Ls[s * LR + 32 + lane] + b2s[32 + lane];
        float m = fmaxf(l0, l1);
#pragma unroll
        for (int off = 16; off; off >>= 1) m = fmaxf(m, __shfl_xor_sync(~0u, m, off));
        float ee0 = __expf(l0 - m), ee1 = __expf(l1 - m);
        float d0 = sd0[s], d1 = sd1[s];
        const float* G0 = Gs + lane * 4;
        const float* G1 = Gs + (lane + 32) * 4;
        float y0 = ee0 * (G0[0] * d0 + G0[1] * d1) + ee1 * (G1[0] * d0 + G1[1] * d1);
        float y1 = ee0 * (G0[2] * d0 + G0[3] * d1) + ee1 * (G1[2] * d0 + G1[3] * d1);
        float Z = ee0 + ee1;
#pragma unroll
        for (int off = 16; off; off >>= 1) {
            y0 += __shfl_xor_sync(~0u, y0, off);
            y1 += __shfl_xor_sync(~0u, y1, off);
            Z += __shfl_xor_sync(~0u, Z, off);
        }
        if (lane == 0) {
            float inv = 1.f / Z;
            out[2 * (base + s) + 0] = y0 * inv;
            out[2 * (base + s) + 1] = y1 * inv;
        }
    }
}

// ---------------------------------------------------------------------------
extern "C" void kernel_launch(void* const* d_in, const int* in_sizes, int n_in,
                              void* d_out, int out_size) {
    const float* x       = (const float*)d_in[0];
    const int*   cls     = (const int*)d_in[1];
    const float* images  = (const float*)d_in[2];
    const float* conv1_w = (const float*)d_in[3];
    const float* conv1_b = (const float*)d_in[4];
    const float* conv2_w = (const float*)d_in[5];
    const float* conv2_b = (const float*)d_in[6];
    const float* fc1_w   = (const float*)d_in[7];
    const float* fc1_b   = (const float*)d_in[8];
    const float* fc2_w   = (const float*)d_in[9];
    const float* fc2_b   = (const float*)d_in[10];
    const float* A_B     = (const float*)d_in[11];
    const float* A_C     = (const float*)d_in[12];
    const float* x_tar   = (const float*)d_in[13];
    float* out = (float*)d_out;

    cudaFuncSetAttribute(conv_kernel, cudaFuncAttributeMaxDynamicSharedMemorySize,
                         K1SMEM);
    cudaFuncSetAttribute(fc1_kernel, cudaFuncAttributeMaxDynamicSharedMemorySize,
                         FC1SMEM);
    cudaFuncSetAttribute(moe_kernel, cudaFuncAttributeMaxDynamicSharedMemorySize,
                         SMEMC);

    conv_kernel<<<K1BLK, 512, K1SMEM>>>(images, conv1_w, conv1_b,
                                        conv2_w, conv2_b, fc1_w, fc2_w);
    fc1_kernel<<<128, 512, FC1SMEM>>>(fc1_w, fc1_b);
    moe_kernel<<<BATCH / 32, 256, SMEMC>>>(x, cls, fc2_b, A_B, A_C, x_tar, out);
    (void)in_sizes; (void)n_in; (void)out_size;
}